// round 1
// baseline (speedup 1.0000x reference)
#include <cuda_runtime.h>
#include <math.h>

// Problem constants
#define BB 64
#define JJ 42
#define PP 16384
#define JG 3            // joint groups
#define JT 14           // joints per group (JG*JT == JJ)
#define PC 4            // P chunks
#define PPB (PP/PC)     // 4096 points per block
#define THREADS 256
#define PPT (PPB/THREADS)   // 16 points per thread
#define NWARP (THREADS/32)

// Scratch for partial per-(b,j) min squared distances (one slot per P-chunk).
__device__ float g_partial[BB * JJ * PC];

__global__ __launch_bounds__(THREADS) void sdl_min_kernel(
    const float* __restrict__ pred,   // [B,J,3]
    const float* __restrict__ pts)    // [B,P,3]
{
    const int blk = blockIdx.x;
    const int pc = blk % PC;
    const int jg = (blk / PC) % JG;
    const int b  = blk / (PC * JG);

    // Load this group's joint constants into registers (uniform across threads).
    float mx[JT], my[JT], mz[JT], a2[JT], acc[JT];
    const float* jp = pred + (size_t)(b * JJ + jg * JT) * 3;
#pragma unroll
    for (int j = 0; j < JT; j++) {
        float ax = jp[j * 3 + 0];
        float ay = jp[j * 3 + 1];
        float az = jp[j * 3 + 2];
        mx[j] = -2.0f * ax;
        my[j] = -2.0f * ay;
        mz[j] = -2.0f * az;
        a2[j] = fmaf(az, az, fmaf(ay, ay, ax * ax));
        acc[j] = 3.0e38f;
    }

    // Points for this (b, pc): 4096 points, float4-aligned vector loads.
    const float4* p4 = (const float4*)(pts + ((size_t)b * PP + (size_t)pc * PPB) * 3);
    const int t = threadIdx.x;

#pragma unroll
    for (int it = 0; it < PPT / 4; it++) {
        // 4 points = 12 floats = 3 float4 loads
        const int f4 = it * (THREADS * 3) + t * 3;
        float4 A = p4[f4 + 0];
        float4 Bv = p4[f4 + 1];
        float4 C = p4[f4 + 2];

        float px[4], py[4], pz[4], b2[4];
        px[0] = A.x;  py[0] = A.y;  pz[0] = A.z;
        px[1] = A.w;  py[1] = Bv.x; pz[1] = Bv.y;
        px[2] = Bv.z; py[2] = Bv.w; pz[2] = C.x;
        px[3] = C.y;  py[3] = C.z;  pz[3] = C.w;
#pragma unroll
        for (int q = 0; q < 4; q++)
            b2[q] = fmaf(pz[q], pz[q], fmaf(py[q], py[q], px[q] * px[q]));

#pragma unroll
        for (int q = 0; q < 4; q++) {
#pragma unroll
            for (int j = 0; j < JT; j++) {
                float tq = fmaf(mx[j], px[q],
                            fmaf(my[j], py[q],
                             fmaf(mz[j], pz[q], b2[q])));
                acc[j] = fminf(acc[j], tq);
            }
        }
    }

    // Fold in a2 (constant shift commutes with min).
#pragma unroll
    for (int j = 0; j < JT; j++) acc[j] += a2[j];

    // Warp min-reduce each joint accumulator.
#pragma unroll
    for (int j = 0; j < JT; j++) {
        float v = acc[j];
        v = fminf(v, __shfl_xor_sync(0xFFFFFFFFu, v, 16));
        v = fminf(v, __shfl_xor_sync(0xFFFFFFFFu, v, 8));
        v = fminf(v, __shfl_xor_sync(0xFFFFFFFFu, v, 4));
        v = fminf(v, __shfl_xor_sync(0xFFFFFFFFu, v, 2));
        v = fminf(v, __shfl_xor_sync(0xFFFFFFFFu, v, 1));
        acc[j] = v;
    }

    __shared__ float smin[NWARP][JT];
    const int w = t >> 5, l = t & 31;
    if (l == 0) {
#pragma unroll
        for (int j = 0; j < JT; j++) smin[w][j] = acc[j];
    }
    __syncthreads();

    if (t < JT) {
        float v = smin[0][t];
#pragma unroll
        for (int wi = 1; wi < NWARP; wi++) v = fminf(v, smin[wi][t]);
        g_partial[(size_t)(b * JJ + jg * JT + t) * PC + pc] = v;
    }
}

__global__ __launch_bounds__(256) void sdl_mse_kernel(
    const float* __restrict__ gt,   // [B,J]
    float* __restrict__ out)
{
    __shared__ float ssum[256];
    const int t = threadIdx.x;
    float s = 0.0f;
    for (int i = t; i < BB * JJ; i += 256) {
        float v = g_partial[(size_t)i * PC + 0];
#pragma unroll
        for (int pc = 1; pc < PC; pc++) v = fminf(v, g_partial[(size_t)i * PC + pc]);
        v = fmaxf(v, 0.0f);
        float d = sqrtf(v);
        float e = d - gt[i];
        s = fmaf(e, e, s);
    }
    ssum[t] = s;
    __syncthreads();
    for (int off = 128; off > 0; off >>= 1) {
        if (t < off) ssum[t] += ssum[t + off];
        __syncthreads();
    }
    if (t == 0) out[0] = ssum[0] / (float)(BB * JJ);
}

extern "C" void kernel_launch(void* const* d_in, const int* in_sizes, int n_in,
                              void* d_out, int out_size) {
    (void)in_sizes; (void)n_in; (void)out_size;
    const float* pred = (const float*)d_in[0];   // [64,42,3]
    const float* pts  = (const float*)d_in[1];   // [64,16384,3]
    const float* gt   = (const float*)d_in[2];   // [64,42]
    float* out = (float*)d_out;

    sdl_min_kernel<<<BB * JG * PC, THREADS>>>(pred, pts);
    sdl_mse_kernel<<<1, 256>>>(gt, out);
}